// round 16
// baseline (speedup 1.0000x reference)
#include <cuda_runtime.h>
#include <cuda_fp16.h>
#include <cstdint>
#include <math.h>

#define BB   32768
#define DRGB 512
#define DSPD 128
#define DIN  640
#define HH   256
#define CC   7

#define BM   128
#define BN   128
#define BK   64
#define NTHR 256
#define STAGE_BYTES 32768        // (128 + 128) rows * 128B
#define NSTAGE 3
#define SMEM_BYTES  (NSTAGE * STAGE_BYTES)

// ---------------- device scratch ----------------
__device__ int g_hpart[128][8];
__device__ int g_off[8];
__device__ int g_pos[8];
__device__ int g_perm[BB];
__device__ int g_off_full[2] = {0, BB};

__device__ __half g_s1[BB * DSPD];
__device__ __half g_s2[BB * DSPD];
__device__ __half g_xbf[(size_t)BB * DIN];     // UNSORTED concat [rgb | sfeat]
__device__ __half g_h1[(size_t)BB * HH];       // sorted space
__device__ __half g_h2[(size_t)BB * HH];
__device__ float4 g_hp[2][BB];                 // per-half head partials {brk,str,thr,_}

// fp16 transposed weights: [C][N][K]
__device__ __half g_W1t[(size_t)CC * HH * DIN];
__device__ __half g_W2t[(size_t)CC * HH * HH];
__device__ __half g_W3t[(size_t)CC * HH * HH];
__device__ __half g_sW2t[DSPD * DSPD];
__device__ __half g_sW3t[DSPD * DSPD];

__device__ __forceinline__ float sigmoidf_(float x) { return 1.0f / (1.0f + expf(-x)); }

// ---------------- PTX helpers ----------------
__device__ __forceinline__ uint32_t smem_u32(const void* p) {
    return (uint32_t)__cvta_generic_to_shared(p);
}
__device__ __forceinline__ void cp_async16(uint32_t dst, const void* src) {
    asm volatile("cp.async.cg.shared.global [%0], [%1], 16;\n" :: "r"(dst), "l"(src) : "memory");
}
__device__ __forceinline__ void cp_commit() { asm volatile("cp.async.commit_group;\n" ::: "memory"); }
template <int N> __device__ __forceinline__ void cp_wait() {
    asm volatile("cp.async.wait_group %0;\n" :: "n"(N) : "memory");
}
__device__ __forceinline__ void ldmx4(uint32_t& r0, uint32_t& r1, uint32_t& r2, uint32_t& r3,
                                      uint32_t addr) {
    asm volatile("ldmatrix.sync.aligned.m8n8.x4.shared.b16 {%0,%1,%2,%3}, [%4];"
                 : "=r"(r0), "=r"(r1), "=r"(r2), "=r"(r3) : "r"(addr));
}
__device__ __forceinline__ void mma16816(float* d, const uint32_t* a, const uint32_t* b) {
    asm volatile(
        "mma.sync.aligned.m16n8k16.row.col.f32.f16.f16.f32 "
        "{%0,%1,%2,%3}, {%4,%5,%6,%7}, {%8,%9}, {%0,%1,%2,%3};"
        : "+f"(d[0]), "+f"(d[1]), "+f"(d[2]), "+f"(d[3])
        : "r"(a[0]), "r"(a[1]), "r"(a[2]), "r"(a[3]), "r"(b[0]), "r"(b[1]));
}
__device__ __forceinline__ uint32_t packh2(float a, float b) {
    __half2 h = __floats2half2_rn(a, b);
    return *(uint32_t*)&h;
}

// ---------------- bucketing ----------------
__global__ void hist_kernel(const int* __restrict__ cmd) {
    __shared__ int sc[8];
    if (threadIdx.x < 8) sc[threadIdx.x] = 0;
    __syncthreads();
    int i = blockIdx.x * blockDim.x + threadIdx.x;
    if (i < BB) atomicAdd(&sc[cmd[i]], 1);
    __syncthreads();
    if (threadIdx.x < 8) g_hpart[blockIdx.x][threadIdx.x] = sc[threadIdx.x];
}

__global__ void scan_kernel() {
    __shared__ int cnt[8];
    int w = threadIdx.x >> 5, lane = threadIdx.x & 31;
    int s = 0;
    for (int k = lane; k < 128; k += 32) s += g_hpart[k][w];
#pragma unroll
    for (int o = 16; o; o >>= 1) s += __shfl_xor_sync(0xFFFFFFFFu, s, o);
    if (lane == 0) cnt[w] = s;
    __syncthreads();
    if (threadIdx.x == 0) {
        g_off[0] = 0;
        for (int c = 0; c < CC; c++) { g_off[c + 1] = g_off[c] + cnt[c]; g_pos[c] = g_off[c]; }
    }
}

__global__ void scatter_kernel(const int* __restrict__ cmd) {
    int i = blockIdx.x * blockDim.x + threadIdx.x;
    if (i >= BB) return;
    int c = cmd[i];
    int lane = threadIdx.x & 31;
    unsigned mask = __match_any_sync(0xFFFFFFFFu, c);
    int leader = __ffs(mask) - 1;
    int rank = __popc(mask & ((1u << lane) - 1));
    int base = 0;
    if (lane == leader) base = atomicAdd(&g_pos[c], __popc(mask));
    base = __shfl_sync(0xFFFFFFFFu, base, leader);
    g_perm[base + rank] = i;
}

// ---------------- weight transpose + fp32->fp16 ----------------
__global__ void transpose_h2_kernel(const float* __restrict__ srcA, __half* __restrict__ dstA,
                                    const float* __restrict__ srcB, __half* __restrict__ dstB,
                                    int R, int C_, int zsplit) {
    __shared__ float t[32][33];
    int z = blockIdx.z;
    const float* src = (z < zsplit) ? srcA : srcB;
    __half* dst = (z < zsplit) ? dstA : dstB;
    int zz = (z < zsplit) ? z : z - zsplit;
    src += (size_t)zz * R * C_;
    dst += (size_t)zz * R * C_;
    int c0 = blockIdx.x * 32, r0 = blockIdx.y * 32;
    int tx = threadIdx.x, ty = threadIdx.y;
#pragma unroll
    for (int k = 0; k < 4; k++)
        t[ty + 8 * k][tx] = src[(size_t)(r0 + ty + 8 * k) * C_ + c0 + tx];
    __syncthreads();
#pragma unroll
    for (int k = 0; k < 4; k++)
        dst[(size_t)(c0 + ty + 8 * k) * R + r0 + tx] = __float2half_rn(t[tx][ty + 8 * k]);
}

// ---------------- speed-MLP layer 1 (rank-1), UNSORTED, fp16 ----------------
__global__ void spd_l1_kernel(const float* __restrict__ spd,
                              const float* __restrict__ W1,
                              const float* __restrict__ b1) {
    int idx = blockIdx.x * blockDim.x + threadIdx.x;
    if (idx >= BB * 16) return;
    int p = idx >> 4;
    int j8 = (idx & 15) * 8;
    float s = spd[p];
    uint4 o;
    float4 w0 = *(const float4*)(W1 + j8), w1 = *(const float4*)(W1 + j8 + 4);
    float4 c0 = *(const float4*)(b1 + j8), c1 = *(const float4*)(b1 + j8 + 4);
    o.x = packh2(tanhf(fmaf(s, w0.x, c0.x)), tanhf(fmaf(s, w0.y, c0.y)));
    o.y = packh2(tanhf(fmaf(s, w0.z, c0.z)), tanhf(fmaf(s, w0.w, c0.w)));
    o.z = packh2(tanhf(fmaf(s, w1.x, c1.x)), tanhf(fmaf(s, w1.y, c1.y)));
    o.w = packh2(tanhf(fmaf(s, w1.z, c1.z)), tanhf(fmaf(s, w1.w, c1.w)));
    *(uint4*)(g_s1 + (size_t)p * DSPD + j8) = o;
}

// ---------------- rgb streaming convert fp32->fp16 (UNSORTED, no perm dep) ----------------
__global__ void convert_rgb_kernel(const float* __restrict__ rgb) {
    int idx = blockIdx.x * blockDim.x + threadIdx.x;
    if (idx >= BB * 64) return;
    int p = idx >> 6;
    int j8 = (idx & 63) * 8;
    float4 v0 = *(const float4*)(rgb + (size_t)p * DRGB + j8);
    float4 v1 = *(const float4*)(rgb + (size_t)p * DRGB + j8 + 4);
    uint4 o;
    o.x = packh2(v0.x, v0.y);
    o.y = packh2(v0.z, v0.w);
    o.z = packh2(v1.x, v1.y);
    o.w = packh2(v1.z, v1.w);
    *(uint4*)(g_xbf + (size_t)p * DIN + j8) = o;
}

// ---------------- fp16 mma.sync GEMM, 3-stage cp.async ----------------
// GATHER: A rows fetched via g_perm. HEADS: skip Out store; emit head dot partials.
template <int K, int NTOT, int ACT, bool GROUPED, bool GATHER, bool HEADS>
__global__ void __launch_bounds__(NTHR)
mma_gemm_kernel(const __half* __restrict__ A,
                const __half* __restrict__ Wt,
                const float* __restrict__ Bbias,
                __half* __restrict__ Out, int out_stride, int coloff,
                const float* __restrict__ hWb, const float* __restrict__ hWs,
                const float* __restrict__ hWt) {
    constexpr int NIT = K / BK;
    const int c = GROUPED ? blockIdx.z : 0;
    const int* off = GROUPED ? g_off : g_off_full;
    const int pstart = off[c];
    const int pend   = off[GROUPED ? (c + 1) : 1];
    const int m0 = pstart + blockIdx.y * BM;
    if (m0 >= pend) return;
    const int n0 = blockIdx.x * BN;

    const __half* W = Wt + ((size_t)c * NTOT + n0) * K;
    const float* bb = Bbias + (size_t)c * NTOT + n0;

    extern __shared__ __align__(16) char smraw[];
    __shared__ float sBias[BN];
    __shared__ int permS[BM];
    __shared__ float sHW[3][BN];

    const int tid  = threadIdx.x;
    const int wid  = tid >> 5;
    const int lane = tid & 31;
    const int wm = (wid >> 2) * 64;
    const int wn = (wid & 3) * 32;

    const uint32_t smBase = smem_u32(smraw);
    if (tid < BN) sBias[tid] = bb[tid];
    if (HEADS && tid < BN) {
        sHW[0][tid] = hWb[c * HH + n0 + tid];
        sHW[1][tid] = hWs[c * HH + n0 + tid];
        sHW[2][tid] = hWt[c * HH + n0 + tid];
    }
    if (GATHER) {
        if (tid < BM) {
            int p = m0 + tid;
            permS[tid] = (p < pend) ? g_perm[p] : g_perm[m0];
        }
        __syncthreads();
    }

    float acc[4][4][4];
#pragma unroll
    for (int i = 0; i < 4; i++)
#pragma unroll
        for (int j = 0; j < 4; j++)
#pragma unroll
            for (int k = 0; k < 4; k++) acc[i][j][k] = 0.f;

    auto prefetch = [&](int it) {
        uint32_t aB = smBase + (uint32_t)(it % NSTAGE) * STAGE_BYTES;
        uint32_t bB = aB + BM * 128;
        int kt = it * BK;
#pragma unroll
        for (int i = 0; i < 4; i++) {
            int idx = tid + i * NTHR;
            int r = idx >> 3;
            int c16 = idx & 7;
            const __half* src;
            if (GATHER) {
                src = A + (size_t)permS[r] * K + kt + c16 * 8;
            } else {
                int p = m0 + r; if (p >= pend) p = m0;
                src = A + (size_t)p * K + kt + c16 * 8;
            }
            cp_async16(aB + r * 128 + (uint32_t)((c16 * 16) ^ ((r & 7) << 4)), src);
        }
#pragma unroll
        for (int i = 0; i < 4; i++) {
            int idx = tid + i * NTHR;
            int r = idx >> 3;
            int c16 = idx & 7;
            const __half* src = W + (size_t)r * K + kt + c16 * 8;
            cp_async16(bB + r * 128 + (uint32_t)((c16 * 16) ^ ((r & 7) << 4)), src);
        }
        cp_commit();
    };

    prefetch(0);
    if (NIT > 1) prefetch(1);

    for (int it = 0; it < NIT; ++it) {
        if (it + 1 < NIT) cp_wait<1>(); else cp_wait<0>();
        __syncthreads();
        if (it + 2 < NIT) prefetch(it + 2);

        uint32_t aB = smBase + (uint32_t)(it % NSTAGE) * STAGE_BYTES;
        uint32_t bB = aB + BM * 128;
#pragma unroll
        for (int ks = 0; ks < BK / 16; ks++) {
            uint32_t a[4][4], b[4][2];
            int cbA = ks * 32 + ((lane >> 4) << 4);
#pragma unroll
            for (int mi = 0; mi < 4; mi++) {
                int r = wm + 16 * mi + (lane & 15);
                ldmx4(a[mi][0], a[mi][1], a[mi][2], a[mi][3],
                      aB + r * 128 + (uint32_t)(cbA ^ ((r & 7) << 4)));
            }
            int cbB = ks * 32 + ((lane & 8) << 1);
#pragma unroll
            for (int nj = 0; nj < 2; nj++) {
                int r = wn + 16 * nj + (lane & 7) + ((lane & 16) >> 1);
                uint32_t t0, t1, t2, t3;
                ldmx4(t0, t1, t2, t3, bB + r * 128 + (uint32_t)(cbB ^ ((r & 7) << 4)));
                b[2 * nj][0] = t0; b[2 * nj][1] = t1;
                b[2 * nj + 1][0] = t2; b[2 * nj + 1][1] = t3;
            }
#pragma unroll
            for (int mi = 0; mi < 4; mi++)
#pragma unroll
                for (int ni = 0; ni < 4; ni++)
                    mma16816(acc[mi][ni], a[mi], b[ni]);
        }
    }
    __syncthreads();

    constexpr int CSTR = 136;
    __half* sC = (__half*)smraw;
#pragma unroll
    for (int mi = 0; mi < 4; mi++) {
        int r0 = wm + 16 * mi + (lane >> 2);
#pragma unroll
        for (int ni = 0; ni < 4; ni++) {
            int col = wn + 8 * ni + 2 * (lane & 3);
            float v0 = acc[mi][ni][0] + sBias[col];
            float v1 = acc[mi][ni][1] + sBias[col + 1];
            float v2 = acc[mi][ni][2] + sBias[col];
            float v3 = acc[mi][ni][3] + sBias[col + 1];
            if (ACT == 0) { v0 = sigmoidf_(v0); v1 = sigmoidf_(v1); v2 = sigmoidf_(v2); v3 = sigmoidf_(v3); }
            else          { v0 = tanhf(v0);     v1 = tanhf(v1);     v2 = tanhf(v2);     v3 = tanhf(v3); }
            *(uint32_t*)(sC + r0 * CSTR + col)       = packh2(v0, v1);
            *(uint32_t*)(sC + (r0 + 8) * CSTR + col) = packh2(v2, v3);
        }
    }
    __syncthreads();

    if (HEADS) {
        // per-row head dot over this block's 128 columns; deterministic order
        const int half = n0 >> 7;
#pragma unroll
        for (int rr = 0; rr < 16; rr++) {
            int r = wid * 16 + rr;
            int p = m0 + r;
            float sb = 0.f, ss = 0.f, st = 0.f;
            int c0 = lane * 4;
#pragma unroll
            for (int j = 0; j < 4; j++) {
                float hv = __half2float(sC[r * CSTR + c0 + j]);
                sb = fmaf(hv, sHW[0][c0 + j], sb);
                ss = fmaf(hv, sHW[1][c0 + j], ss);
                st = fmaf(hv, sHW[2][c0 + j], st);
            }
#pragma unroll
            for (int o = 16; o; o >>= 1) {
                sb += __shfl_xor_sync(0xFFFFFFFFu, sb, o);
                ss += __shfl_xor_sync(0xFFFFFFFFu, ss, o);
                st += __shfl_xor_sync(0xFFFFFFFFu, st, o);
            }
            if (lane == 0 && p < pend) g_hp[half][p] = make_float4(sb, ss, st, 0.f);
        }
    } else {
#pragma unroll
        for (int i = 0; i < 8; i++) {
            int e = tid + i * NTHR;
            int r = e >> 4, q = e & 15;
            int p = m0 + r;
            if (p < pend) {
                uint4 v = *(const uint4*)(sC + r * CSTR + q * 8);
                *(uint4*)(Out + (size_t)p * out_stride + coloff + n0 + q * 8) = v;
            }
        }
    }
}

// ---------------- heads finalize ----------------
__global__ void heads_fin_kernel(const int* __restrict__ cmd,
                                 const float* __restrict__ hbb,
                                 const float* __restrict__ hbs,
                                 const float* __restrict__ hbt,
                                 float* __restrict__ out) {
    int p = blockIdx.x * blockDim.x + threadIdx.x;
    if (p >= BB) return;
    int r = g_perm[p];
    int c = cmd[r];
    float4 a = g_hp[0][p];
    float4 b = g_hp[1][p];
    out[r]          = sigmoidf_(a.x + b.x + hbb[c]);
    out[BB + r]     = tanhf(a.y + b.y + hbs[c]);
    out[2 * BB + r] = sigmoidf_(a.z + b.z + hbt[c]);
}

// ---------------- launcher ----------------
extern "C" void kernel_launch(void* const* d_in, const int* in_sizes, int n_in,
                              void* d_out, int out_size) {
    const float* rgb  = (const float*)d_in[0];
    const float* spd  = (const float*)d_in[1];
    const int*   cmd  = (const int*)  d_in[2];
    const float* sW1  = (const float*)d_in[3];
    const float* sb1  = (const float*)d_in[4];
    const float* sW2  = (const float*)d_in[5];
    const float* sb2  = (const float*)d_in[6];
    const float* sW3  = (const float*)d_in[7];
    const float* sb3  = (const float*)d_in[8];
    const float* W1   = (const float*)d_in[9];
    const float* b1   = (const float*)d_in[10];
    const float* W2   = (const float*)d_in[11];
    const float* b2   = (const float*)d_in[12];
    const float* W3   = (const float*)d_in[13];
    const float* b3   = (const float*)d_in[14];
    const float* hWb  = (const float*)d_in[15];
    const float* hbb  = (const float*)d_in[16];
    const float* hWs  = (const float*)d_in[17];
    const float* hbs  = (const float*)d_in[18];
    const float* hWt  = (const float*)d_in[19];
    const float* hbt  = (const float*)d_in[20];
    float* out = (float*)d_out;

    void* p;
    cudaGetSymbolAddress(&p, g_s1);   __half* s1  = (__half*)p;
    cudaGetSymbolAddress(&p, g_s2);   __half* s2  = (__half*)p;
    cudaGetSymbolAddress(&p, g_xbf);  __half* xbf = (__half*)p;
    cudaGetSymbolAddress(&p, g_h1);   __half* h1  = (__half*)p;
    cudaGetSymbolAddress(&p, g_h2);   __half* h2  = (__half*)p;
    cudaGetSymbolAddress(&p, g_W1t);  __half* W1t = (__half*)p;
    cudaGetSymbolAddress(&p, g_W2t);  __half* W2t = (__half*)p;
    cudaGetSymbolAddress(&p, g_W3t);  __half* W3t = (__half*)p;
    cudaGetSymbolAddress(&p, g_sW2t); __half* sW2t = (__half*)p;
    cudaGetSymbolAddress(&p, g_sW3t); __half* sW3t = (__half*)p;

    cudaFuncSetAttribute(mma_gemm_kernel<DSPD, DSPD, 1, false, false, false>,
                         cudaFuncAttributeMaxDynamicSharedMemorySize, SMEM_BYTES);
    cudaFuncSetAttribute(mma_gemm_kernel<DIN, HH, 0, true, true, false>,
                         cudaFuncAttributeMaxDynamicSharedMemorySize, SMEM_BYTES);
    cudaFuncSetAttribute(mma_gemm_kernel<HH, HH, 0, true, false, false>,
                         cudaFuncAttributeMaxDynamicSharedMemorySize, SMEM_BYTES);
    cudaFuncSetAttribute(mma_gemm_kernel<HH, HH, 0, true, false, true>,
                         cudaFuncAttributeMaxDynamicSharedMemorySize, SMEM_BYTES);

    static cudaStream_t sT = nullptr, sS = nullptr, sG = nullptr;
    static cudaEvent_t evRoot = nullptr, evT = nullptr, evTs = nullptr, evSpd = nullptr, evG = nullptr;
    if (sT == nullptr) {
        cudaStreamCreateWithFlags(&sT, cudaStreamNonBlocking);
        cudaStreamCreateWithFlags(&sS, cudaStreamNonBlocking);
        cudaStreamCreateWithFlags(&sG, cudaStreamNonBlocking);
        cudaEventCreateWithFlags(&evRoot, cudaEventDisableTiming);
        cudaEventCreateWithFlags(&evT,    cudaEventDisableTiming);
        cudaEventCreateWithFlags(&evTs,   cudaEventDisableTiming);
        cudaEventCreateWithFlags(&evSpd,  cudaEventDisableTiming);
        cudaEventCreateWithFlags(&evG,    cudaEventDisableTiming);
    }

    cudaEventRecord(evRoot, 0);
    cudaStreamWaitEvent(sT, evRoot, 0);
    cudaStreamWaitEvent(sS, evRoot, 0);
    cudaStreamWaitEvent(sG, evRoot, 0);

    // sT: small speed-weight transpose FIRST (unblocks spd chain), then big ones
    {
        dim3 b(32, 8);
        transpose_h2_kernel<<<dim3(DSPD / 32, DSPD / 32, 2), b, 0, sT>>>(sW2, sW2t, sW3, sW3t, DSPD, DSPD, 1);
        cudaEventRecord(evTs, sT);
        transpose_h2_kernel<<<dim3(HH / 32, DIN / 32, CC), b, 0, sT>>>(W1, W1t, W1, W1t, DIN, HH, CC);
        transpose_h2_kernel<<<dim3(HH / 32, HH / 32, 2 * CC), b, 0, sT>>>(W2, W2t, W3, W3t, HH, HH, CC);
        cudaEventRecord(evT, sT);
    }

    // sG: rgb fp32->fp16 streaming convert (unsorted, independent of bucketing)
    convert_rgb_kernel<<<(BB * 64) / 256, 256, 0, sG>>>(rgb);
    cudaEventRecord(evG, sG);

    // sS: speed branch, unsorted (GEMMs wait only on the small transpose)
    spd_l1_kernel<<<(BB * 16) / 256, 256, 0, sS>>>(spd, sW1, sb1);
    cudaStreamWaitEvent(sS, evTs, 0);
    {
        dim3 g(1, BB / BM, 1);
        mma_gemm_kernel<DSPD, DSPD, 1, false, false, false><<<g, NTHR, SMEM_BYTES, sS>>>(
            s1, sW2t, sb2, s2, DSPD, 0, nullptr, nullptr, nullptr);
        mma_gemm_kernel<DSPD, DSPD, 1, false, false, false><<<g, NTHR, SMEM_BYTES, sS>>>(
            s2, sW3t, sb3, xbf, DIN, DRGB, nullptr, nullptr, nullptr);
    }
    cudaEventRecord(evSpd, sS);

    // default stream: bucketing
    hist_kernel<<<BB / 256, 256>>>(cmd);
    scan_kernel<<<1, 256>>>();
    scatter_kernel<<<BB / 256, 256>>>(cmd);

    // join: L1 needs perm + xbf (rgb conv + spd chain) + W1t
    cudaStreamWaitEvent(0, evT, 0);
    cudaStreamWaitEvent(0, evG, 0);
    cudaStreamWaitEvent(0, evSpd, 0);

    // branch MLPs (L1 gathers A rows through perm; L3 emits head partials)
    {
        dim3 g1(HH / BN, BB / BM, CC);
        mma_gemm_kernel<DIN, HH, 0, true, true, false><<<g1, NTHR, SMEM_BYTES>>>(
            xbf, W1t, b1, h1, HH, 0, nullptr, nullptr, nullptr);
        mma_gemm_kernel<HH, HH, 0, true, false, false><<<g1, NTHR, SMEM_BYTES>>>(
            h1, W2t, b2, h2, HH, 0, nullptr, nullptr, nullptr);
        mma_gemm_kernel<HH, HH, 0, true, false, true><<<g1, NTHR, SMEM_BYTES>>>(
            h2, W3t, b3, nullptr, HH, 0, hWb, hWs, hWt);
    }

    // heads finalize
    heads_fin_kernel<<<BB / 256, 256>>>(cmd, hbb, hbs, hbt, out);
}

// round 17
// speedup vs baseline: 1.2414x; 1.2414x over previous
#include <cuda_runtime.h>
#include <cuda_fp16.h>
#include <cstdint>
#include <math.h>

#define BB   32768
#define DRGB 512
#define DSPD 128
#define DIN  640
#define HH   256
#define CC   7

#define BM   128
#define BN   128
#define BK   64
#define NTHR 256
#define STAGE_BYTES 32768        // (128 + 128) rows * 128B
#define NSTAGE 3
#define SMEM_BYTES  (NSTAGE * STAGE_BYTES)

// ---------------- device scratch ----------------
__device__ int g_hpart[128][8];
__device__ int g_off[8];
__device__ int g_pos[8];
__device__ int g_perm[BB];
__device__ int g_off_full[2] = {0, BB};

__device__ __half g_s1[BB * DSPD];
__device__ __half g_s2[BB * DSPD];
__device__ __half g_xbf[(size_t)BB * DIN];     // UNSORTED concat [rgb | sfeat]
__device__ __half g_h1[(size_t)BB * HH];       // sorted space
__device__ __half g_h2[(size_t)BB * HH];
__device__ float4 g_hp[2][BB];                 // per-half head partials {brk,str,thr,_}

// fp16 transposed weights: [C][N][K]
__device__ __half g_W1t[(size_t)CC * HH * DIN];
__device__ __half g_W2t[(size_t)CC * HH * HH];
__device__ __half g_W3t[(size_t)CC * HH * HH];
__device__ __half g_sW2t[DSPD * DSPD];
__device__ __half g_sW3t[DSPD * DSPD];

// exact activations (outputs only)
__device__ __forceinline__ float sigmoidf_(float x) { return 1.0f / (1.0f + expf(-x)); }
// fast internal activations (single MUFU.TANH)
__device__ __forceinline__ float tanh_fast(float x) {
    float y; asm("tanh.approx.f32 %0, %1;" : "=f"(y) : "f"(x)); return y;
}
__device__ __forceinline__ float sigmoid_fast(float x) {
    return fmaf(0.5f, tanh_fast(0.5f * x), 0.5f);
}

// ---------------- PTX helpers ----------------
__device__ __forceinline__ uint32_t smem_u32(const void* p) {
    return (uint32_t)__cvta_generic_to_shared(p);
}
__device__ __forceinline__ void cp_async16(uint32_t dst, const void* src) {
    asm volatile("cp.async.cg.shared.global [%0], [%1], 16;\n" :: "r"(dst), "l"(src) : "memory");
}
__device__ __forceinline__ void cp_commit() { asm volatile("cp.async.commit_group;\n" ::: "memory"); }
template <int N> __device__ __forceinline__ void cp_wait() {
    asm volatile("cp.async.wait_group %0;\n" :: "n"(N) : "memory");
}
__device__ __forceinline__ void ldmx4(uint32_t& r0, uint32_t& r1, uint32_t& r2, uint32_t& r3,
                                      uint32_t addr) {
    asm volatile("ldmatrix.sync.aligned.m8n8.x4.shared.b16 {%0,%1,%2,%3}, [%4];"
                 : "=r"(r0), "=r"(r1), "=r"(r2), "=r"(r3) : "r"(addr));
}
__device__ __forceinline__ void mma16816(float* d, const uint32_t* a, const uint32_t* b) {
    asm volatile(
        "mma.sync.aligned.m16n8k16.row.col.f32.f16.f16.f32 "
        "{%0,%1,%2,%3}, {%4,%5,%6,%7}, {%8,%9}, {%0,%1,%2,%3};"
        : "+f"(d[0]), "+f"(d[1]), "+f"(d[2]), "+f"(d[3])
        : "r"(a[0]), "r"(a[1]), "r"(a[2]), "r"(a[3]), "r"(b[0]), "r"(b[1]));
}
__device__ __forceinline__ uint32_t packh2(float a, float b) {
    __half2 h = __floats2half2_rn(a, b);
    return *(uint32_t*)&h;
}

// ---------------- bucketing ----------------
__global__ void hist_kernel(const int* __restrict__ cmd) {
    __shared__ int sc[8];
    if (threadIdx.x < 8) sc[threadIdx.x] = 0;
    __syncthreads();
    int i = blockIdx.x * blockDim.x + threadIdx.x;
    if (i < BB) atomicAdd(&sc[cmd[i]], 1);
    __syncthreads();
    if (threadIdx.x < 8) g_hpart[blockIdx.x][threadIdx.x] = sc[threadIdx.x];
}

__global__ void scan_kernel() {
    __shared__ int cnt[8];
    int w = threadIdx.x >> 5, lane = threadIdx.x & 31;
    int s = 0;
    for (int k = lane; k < 128; k += 32) s += g_hpart[k][w];
#pragma unroll
    for (int o = 16; o; o >>= 1) s += __shfl_xor_sync(0xFFFFFFFFu, s, o);
    if (lane == 0) cnt[w] = s;
    __syncthreads();
    if (threadIdx.x == 0) {
        g_off[0] = 0;
        for (int c = 0; c < CC; c++) { g_off[c + 1] = g_off[c] + cnt[c]; g_pos[c] = g_off[c]; }
    }
}

__global__ void scatter_kernel(const int* __restrict__ cmd) {
    int i = blockIdx.x * blockDim.x + threadIdx.x;
    if (i >= BB) return;
    int c = cmd[i];
    int lane = threadIdx.x & 31;
    unsigned mask = __match_any_sync(0xFFFFFFFFu, c);
    int leader = __ffs(mask) - 1;
    int rank = __popc(mask & ((1u << lane) - 1));
    int base = 0;
    if (lane == leader) base = atomicAdd(&g_pos[c], __popc(mask));
    base = __shfl_sync(0xFFFFFFFFu, base, leader);
    g_perm[base + rank] = i;
}

// ---------------- weight transpose + fp32->fp16 ----------------
__global__ void transpose_h2_kernel(const float* __restrict__ srcA, __half* __restrict__ dstA,
                                    const float* __restrict__ srcB, __half* __restrict__ dstB,
                                    int R, int C_, int zsplit) {
    __shared__ float t[32][33];
    int z = blockIdx.z;
    const float* src = (z < zsplit) ? srcA : srcB;
    __half* dst = (z < zsplit) ? dstA : dstB;
    int zz = (z < zsplit) ? z : z - zsplit;
    src += (size_t)zz * R * C_;
    dst += (size_t)zz * R * C_;
    int c0 = blockIdx.x * 32, r0 = blockIdx.y * 32;
    int tx = threadIdx.x, ty = threadIdx.y;
#pragma unroll
    for (int k = 0; k < 4; k++)
        t[ty + 8 * k][tx] = src[(size_t)(r0 + ty + 8 * k) * C_ + c0 + tx];
    __syncthreads();
#pragma unroll
    for (int k = 0; k < 4; k++)
        dst[(size_t)(c0 + ty + 8 * k) * R + r0 + tx] = __float2half_rn(t[tx][ty + 8 * k]);
}

// ---------------- speed-MLP layer 1 (rank-1), UNSORTED, fp16 ----------------
__global__ void spd_l1_kernel(const float* __restrict__ spd,
                              const float* __restrict__ W1,
                              const float* __restrict__ b1) {
    int idx = blockIdx.x * blockDim.x + threadIdx.x;
    if (idx >= BB * 16) return;
    int p = idx >> 4;
    int j8 = (idx & 15) * 8;
    float s = spd[p];
    uint4 o;
    float4 w0 = *(const float4*)(W1 + j8), w1 = *(const float4*)(W1 + j8 + 4);
    float4 c0 = *(const float4*)(b1 + j8), c1 = *(const float4*)(b1 + j8 + 4);
    o.x = packh2(tanh_fast(fmaf(s, w0.x, c0.x)), tanh_fast(fmaf(s, w0.y, c0.y)));
    o.y = packh2(tanh_fast(fmaf(s, w0.z, c0.z)), tanh_fast(fmaf(s, w0.w, c0.w)));
    o.z = packh2(tanh_fast(fmaf(s, w1.x, c1.x)), tanh_fast(fmaf(s, w1.y, c1.y)));
    o.w = packh2(tanh_fast(fmaf(s, w1.z, c1.z)), tanh_fast(fmaf(s, w1.w, c1.w)));
    *(uint4*)(g_s1 + (size_t)p * DSPD + j8) = o;
}

// ---------------- rgb streaming convert fp32->fp16 (UNSORTED, no perm dep) ----------------
__global__ void convert_rgb_kernel(const float* __restrict__ rgb) {
    int idx = blockIdx.x * blockDim.x + threadIdx.x;
    if (idx >= BB * 64) return;
    int p = idx >> 6;
    int j8 = (idx & 63) * 8;
    float4 v0 = *(const float4*)(rgb + (size_t)p * DRGB + j8);
    float4 v1 = *(const float4*)(rgb + (size_t)p * DRGB + j8 + 4);
    uint4 o;
    o.x = packh2(v0.x, v0.y);
    o.y = packh2(v0.z, v0.w);
    o.z = packh2(v1.x, v1.y);
    o.w = packh2(v1.z, v1.w);
    *(uint4*)(g_xbf + (size_t)p * DIN + j8) = o;
}

// ---------------- fp16 mma.sync GEMM, 3-stage cp.async ----------------
// GATHER: A rows fetched via g_perm. HEADS: skip Out store; emit head dot partials.
template <int K, int NTOT, int ACT, bool GROUPED, bool GATHER, bool HEADS>
__global__ void __launch_bounds__(NTHR)
mma_gemm_kernel(const __half* __restrict__ A,
                const __half* __restrict__ Wt,
                const float* __restrict__ Bbias,
                __half* __restrict__ Out, int out_stride, int coloff,
                const float* __restrict__ hWb, const float* __restrict__ hWs,
                const float* __restrict__ hWt) {
    constexpr int NIT = K / BK;
    const int c = GROUPED ? blockIdx.z : 0;
    const int* off = GROUPED ? g_off : g_off_full;
    const int pstart = off[c];
    const int pend   = off[GROUPED ? (c + 1) : 1];
    const int m0 = pstart + blockIdx.y * BM;
    if (m0 >= pend) return;
    const int n0 = blockIdx.x * BN;

    const __half* W = Wt + ((size_t)c * NTOT + n0) * K;
    const float* bb = Bbias + (size_t)c * NTOT + n0;

    extern __shared__ __align__(16) char smraw[];
    __shared__ float sBias[BN];
    __shared__ int permS[BM];
    __shared__ float sHW[3][BN];

    const int tid  = threadIdx.x;
    const int wid  = tid >> 5;
    const int lane = tid & 31;
    const int wm = (wid >> 2) * 64;
    const int wn = (wid & 3) * 32;

    const uint32_t smBase = smem_u32(smraw);
    if (tid < BN) sBias[tid] = bb[tid];
    if (HEADS && tid < BN) {
        sHW[0][tid] = hWb[c * HH + n0 + tid];
        sHW[1][tid] = hWs[c * HH + n0 + tid];
        sHW[2][tid] = hWt[c * HH + n0 + tid];
    }
    if (GATHER) {
        if (tid < BM) {
            int p = m0 + tid;
            permS[tid] = (p < pend) ? g_perm[p] : g_perm[m0];
        }
        __syncthreads();
    }

    float acc[4][4][4];
#pragma unroll
    for (int i = 0; i < 4; i++)
#pragma unroll
        for (int j = 0; j < 4; j++)
#pragma unroll
            for (int k = 0; k < 4; k++) acc[i][j][k] = 0.f;

    auto prefetch = [&](int it) {
        uint32_t aB = smBase + (uint32_t)(it % NSTAGE) * STAGE_BYTES;
        uint32_t bB = aB + BM * 128;
        int kt = it * BK;
#pragma unroll
        for (int i = 0; i < 4; i++) {
            int idx = tid + i * NTHR;
            int r = idx >> 3;
            int c16 = idx & 7;
            const __half* src;
            if (GATHER) {
                src = A + (size_t)permS[r] * K + kt + c16 * 8;
            } else {
                int p = m0 + r; if (p >= pend) p = m0;
                src = A + (size_t)p * K + kt + c16 * 8;
            }
            cp_async16(aB + r * 128 + (uint32_t)((c16 * 16) ^ ((r & 7) << 4)), src);
        }
#pragma unroll
        for (int i = 0; i < 4; i++) {
            int idx = tid + i * NTHR;
            int r = idx >> 3;
            int c16 = idx & 7;
            const __half* src = W + (size_t)r * K + kt + c16 * 8;
            cp_async16(bB + r * 128 + (uint32_t)((c16 * 16) ^ ((r & 7) << 4)), src);
        }
        cp_commit();
    };

    prefetch(0);
    if (NIT > 1) prefetch(1);

    for (int it = 0; it < NIT; ++it) {
        if (it + 1 < NIT) cp_wait<1>(); else cp_wait<0>();
        __syncthreads();
        if (it + 2 < NIT) prefetch(it + 2);

        uint32_t aB = smBase + (uint32_t)(it % NSTAGE) * STAGE_BYTES;
        uint32_t bB = aB + BM * 128;
#pragma unroll
        for (int ks = 0; ks < BK / 16; ks++) {
            uint32_t a[4][4], b[4][2];
            int cbA = ks * 32 + ((lane >> 4) << 4);
#pragma unroll
            for (int mi = 0; mi < 4; mi++) {
                int r = wm + 16 * mi + (lane & 15);
                ldmx4(a[mi][0], a[mi][1], a[mi][2], a[mi][3],
                      aB + r * 128 + (uint32_t)(cbA ^ ((r & 7) << 4)));
            }
            int cbB = ks * 32 + ((lane & 8) << 1);
#pragma unroll
            for (int nj = 0; nj < 2; nj++) {
                int r = wn + 16 * nj + (lane & 7) + ((lane & 16) >> 1);
                uint32_t t0, t1, t2, t3;
                ldmx4(t0, t1, t2, t3, bB + r * 128 + (uint32_t)(cbB ^ ((r & 7) << 4)));
                b[2 * nj][0] = t0; b[2 * nj][1] = t1;
                b[2 * nj + 1][0] = t2; b[2 * nj + 1][1] = t3;
            }
#pragma unroll
            for (int mi = 0; mi < 4; mi++)
#pragma unroll
                for (int ni = 0; ni < 4; ni++)
                    mma16816(acc[mi][ni], a[mi], b[ni]);
        }
    }
    __syncthreads();

    constexpr int CSTR = 136;
    __half* sC = (__half*)smraw;
#pragma unroll
    for (int mi = 0; mi < 4; mi++) {
        int r0 = wm + 16 * mi + (lane >> 2);
#pragma unroll
        for (int ni = 0; ni < 4; ni++) {
            int col = wn + 8 * ni + 2 * (lane & 3);
            float v0 = acc[mi][ni][0] + sBias[col];
            float v1 = acc[mi][ni][1] + sBias[col + 1];
            float v2 = acc[mi][ni][2] + sBias[col];
            float v3 = acc[mi][ni][3] + sBias[col + 1];
            if (ACT == 0) { v0 = sigmoid_fast(v0); v1 = sigmoid_fast(v1); v2 = sigmoid_fast(v2); v3 = sigmoid_fast(v3); }
            else          { v0 = tanh_fast(v0);    v1 = tanh_fast(v1);    v2 = tanh_fast(v2);    v3 = tanh_fast(v3); }
            *(uint32_t*)(sC + r0 * CSTR + col)       = packh2(v0, v1);
            *(uint32_t*)(sC + (r0 + 8) * CSTR + col) = packh2(v2, v3);
        }
    }
    __syncthreads();

    if (HEADS) {
        // per-row head dot over this block's 128 columns; deterministic order
        const int half = n0 >> 7;
#pragma unroll
        for (int rr = 0; rr < 16; rr++) {
            int r = wid * 16 + rr;
            int p = m0 + r;
            float sb = 0.f, ss = 0.f, st = 0.f;
            int c0 = lane * 4;
#pragma unroll
            for (int j = 0; j < 4; j++) {
                float hv = __half2float(sC[r * CSTR + c0 + j]);
                sb = fmaf(hv, sHW[0][c0 + j], sb);
                ss = fmaf(hv, sHW[1][c0 + j], ss);
                st = fmaf(hv, sHW[2][c0 + j], st);
            }
#pragma unroll
            for (int o = 16; o; o >>= 1) {
                sb += __shfl_xor_sync(0xFFFFFFFFu, sb, o);
                ss += __shfl_xor_sync(0xFFFFFFFFu, ss, o);
                st += __shfl_xor_sync(0xFFFFFFFFu, st, o);
            }
            if (lane == 0 && p < pend) g_hp[half][p] = make_float4(sb, ss, st, 0.f);
        }
    } else {
#pragma unroll
        for (int i = 0; i < 8; i++) {
            int e = tid + i * NTHR;
            int r = e >> 4, q = e & 15;
            int p = m0 + r;
            if (p < pend) {
                uint4 v = *(const uint4*)(sC + r * CSTR + q * 8);
                *(uint4*)(Out + (size_t)p * out_stride + coloff + n0 + q * 8) = v;
            }
        }
    }
}

// ---------------- heads finalize (exact activations) ----------------
__global__ void heads_fin_kernel(const int* __restrict__ cmd,
                                 const float* __restrict__ hbb,
                                 const float* __restrict__ hbs,
                                 const float* __restrict__ hbt,
                                 float* __restrict__ out) {
    int p = blockIdx.x * blockDim.x + threadIdx.x;
    if (p >= BB) return;
    int r = g_perm[p];
    int c = cmd[r];
    float4 a = g_hp[0][p];
    float4 b = g_hp[1][p];
    out[r]          = sigmoidf_(a.x + b.x + hbb[c]);
    out[BB + r]     = tanhf(a.y + b.y + hbs[c]);
    out[2 * BB + r] = sigmoidf_(a.z + b.z + hbt[c]);
}

// ---------------- launcher ----------------
extern "C" void kernel_launch(void* const* d_in, const int* in_sizes, int n_in,
                              void* d_out, int out_size) {
    const float* rgb  = (const float*)d_in[0];
    const float* spd  = (const float*)d_in[1];
    const int*   cmd  = (const int*)  d_in[2];
    const float* sW1  = (const float*)d_in[3];
    const float* sb1  = (const float*)d_in[4];
    const float* sW2  = (const float*)d_in[5];
    const float* sb2  = (const float*)d_in[6];
    const float* sW3  = (const float*)d_in[7];
    const float* sb3  = (const float*)d_in[8];
    const float* W1   = (const float*)d_in[9];
    const float* b1   = (const float*)d_in[10];
    const float* W2   = (const float*)d_in[11];
    const float* b2   = (const float*)d_in[12];
    const float* W3   = (const float*)d_in[13];
    const float* b3   = (const float*)d_in[14];
    const float* hWb  = (const float*)d_in[15];
    const float* hbb  = (const float*)d_in[16];
    const float* hWs  = (const float*)d_in[17];
    const float* hbs  = (const float*)d_in[18];
    const float* hWt  = (const float*)d_in[19];
    const float* hbt  = (const float*)d_in[20];
    float* out = (float*)d_out;

    void* p;
    cudaGetSymbolAddress(&p, g_s1);   __half* s1  = (__half*)p;
    cudaGetSymbolAddress(&p, g_s2);   __half* s2  = (__half*)p;
    cudaGetSymbolAddress(&p, g_xbf);  __half* xbf = (__half*)p;
    cudaGetSymbolAddress(&p, g_h1);   __half* h1  = (__half*)p;
    cudaGetSymbolAddress(&p, g_h2);   __half* h2  = (__half*)p;
    cudaGetSymbolAddress(&p, g_W1t);  __half* W1t = (__half*)p;
    cudaGetSymbolAddress(&p, g_W2t);  __half* W2t = (__half*)p;
    cudaGetSymbolAddress(&p, g_W3t);  __half* W3t = (__half*)p;
    cudaGetSymbolAddress(&p, g_sW2t); __half* sW2t = (__half*)p;
    cudaGetSymbolAddress(&p, g_sW3t); __half* sW3t = (__half*)p;

    cudaFuncSetAttribute(mma_gemm_kernel<DSPD, DSPD, 1, false, false, false>,
                         cudaFuncAttributeMaxDynamicSharedMemorySize, SMEM_BYTES);
    cudaFuncSetAttribute(mma_gemm_kernel<DIN, HH, 0, true, true, false>,
                         cudaFuncAttributeMaxDynamicSharedMemorySize, SMEM_BYTES);
    cudaFuncSetAttribute(mma_gemm_kernel<HH, HH, 0, true, false, false>,
                         cudaFuncAttributeMaxDynamicSharedMemorySize, SMEM_BYTES);
    cudaFuncSetAttribute(mma_gemm_kernel<HH, HH, 0, true, false, true>,
                         cudaFuncAttributeMaxDynamicSharedMemorySize, SMEM_BYTES);

    static cudaStream_t sT = nullptr, sS = nullptr, sG = nullptr;
    static cudaEvent_t evRoot = nullptr, evT = nullptr, evTs = nullptr, evSpd = nullptr, evG = nullptr;
    if (sT == nullptr) {
        cudaStreamCreateWithFlags(&sT, cudaStreamNonBlocking);
        cudaStreamCreateWithFlags(&sS, cudaStreamNonBlocking);
        cudaStreamCreateWithFlags(&sG, cudaStreamNonBlocking);
        cudaEventCreateWithFlags(&evRoot, cudaEventDisableTiming);
        cudaEventCreateWithFlags(&evT,    cudaEventDisableTiming);
        cudaEventCreateWithFlags(&evTs,   cudaEventDisableTiming);
        cudaEventCreateWithFlags(&evSpd,  cudaEventDisableTiming);
        cudaEventCreateWithFlags(&evG,    cudaEventDisableTiming);
    }

    cudaEventRecord(evRoot, 0);
    cudaStreamWaitEvent(sT, evRoot, 0);
    cudaStreamWaitEvent(sS, evRoot, 0);
    cudaStreamWaitEvent(sG, evRoot, 0);

    // sT: small speed-weight transpose FIRST (unblocks spd chain), then big ones
    {
        dim3 b(32, 8);
        transpose_h2_kernel<<<dim3(DSPD / 32, DSPD / 32, 2), b, 0, sT>>>(sW2, sW2t, sW3, sW3t, DSPD, DSPD, 1);
        cudaEventRecord(evTs, sT);
        transpose_h2_kernel<<<dim3(HH / 32, DIN / 32, CC), b, 0, sT>>>(W1, W1t, W1, W1t, DIN, HH, CC);
        transpose_h2_kernel<<<dim3(HH / 32, HH / 32, 2 * CC), b, 0, sT>>>(W2, W2t, W3, W3t, HH, HH, CC);
        cudaEventRecord(evT, sT);
    }

    // sG: rgb fp32->fp16 streaming convert (unsorted, independent of bucketing)
    convert_rgb_kernel<<<(BB * 64) / 256, 256, 0, sG>>>(rgb);
    cudaEventRecord(evG, sG);

    // sS: speed branch, unsorted (GEMMs wait only on the small transpose)
    spd_l1_kernel<<<(BB * 16) / 256, 256, 0, sS>>>(spd, sW1, sb1);
    cudaStreamWaitEvent(sS, evTs, 0);
    {
        dim3 g(1, BB / BM, 1);
        mma_gemm_kernel<DSPD, DSPD, 1, false, false, false><<<g, NTHR, SMEM_BYTES, sS>>>(
            s1, sW2t, sb2, s2, DSPD, 0, nullptr, nullptr, nullptr);
        mma_gemm_kernel<DSPD, DSPD, 1, false, false, false><<<g, NTHR, SMEM_BYTES, sS>>>(
            s2, sW3t, sb3, xbf, DIN, DRGB, nullptr, nullptr, nullptr);
    }
    cudaEventRecord(evSpd, sS);

    // default stream: bucketing
    hist_kernel<<<BB / 256, 256>>>(cmd);
    scan_kernel<<<1, 256>>>();
    scatter_kernel<<<BB / 256, 256>>>(cmd);

    // join: L1 needs perm + xbf (rgb conv + spd chain) + W1t
    cudaStreamWaitEvent(0, evT, 0);
    cudaStreamWaitEvent(0, evG, 0);
    cudaStreamWaitEvent(0, evSpd, 0);

    // branch MLPs (L1 gathers A rows through perm; L3 emits head partials)
    {
        dim3 g1(HH / BN, BB / BM, CC);
        mma_gemm_kernel<DIN, HH, 0, true, true, false><<<g1, NTHR, SMEM_BYTES>>>(
            xbf, W1t, b1, h1, HH, 0, nullptr, nullptr, nullptr);
        mma_gemm_kernel<HH, HH, 0, true, false, false><<<g1, NTHR, SMEM_BYTES>>>(
            h1, W2t, b2, h2, HH, 0, nullptr, nullptr, nullptr);
        mma_gemm_kernel<HH, HH, 0, true, false, true><<<g1, NTHR, SMEM_BYTES>>>(
            h2, W3t, b3, nullptr, HH, 0, hWb, hWs, hWt);
    }

    // heads finalize
    heads_fin_kernel<<<BB / 256, 256>>>(cmd, hbb, hbs, hbt, out);
}